// round 2
// baseline (speedup 1.0000x reference)
#include <cuda_runtime.h>
#include <math.h>

#define NF 16          // B*S
#define AA 24000
#define CC 80
#define MM 20
#define CE 7
#define TA 64          // anchors per block in main kernel
#define MB 8           // blocks per frame in match kernel

// ---- device scratch (no allocations allowed) ----
__device__ float              g_bt_iou[NF * AA];
__device__ int                g_bt_idx[NF * AA];
__device__ unsigned long long g_gt_key[NF * MM];
__device__ double             g_cls_sum;
__device__ double             g_reg_sum;
__device__ int                g_pos_cnt;
__device__ float              g_w[CC];

// ---------------- K0: init accumulators + class-balance weights ----------------
__global__ void k0_init(const int* __restrict__ cls_num_list) {
    int tid = threadIdx.x;
    __shared__ float sraw[128];
    __shared__ float ssum;
    float raw = 0.f;
    if (tid < CC) {
        double beta = (double)0.9999f;   // match f32-rounded constant
        double n = (double)cls_num_list[tid];
        raw = (float)((1.0 - beta) / (1.0 - pow(beta, n)));
    }
    sraw[tid] = raw;
    __syncthreads();
    for (int s = 64; s > 0; s >>= 1) {
        if (tid < s) sraw[tid] += sraw[tid + s];
        __syncthreads();
    }
    if (tid == 0) {
        ssum = sraw[0];
        g_cls_sum = 0.0;
        g_reg_sum = 0.0;
        g_pos_cnt = 0;
    }
    __syncthreads();
    if (tid < CC) g_w[tid] = raw / ssum;
    for (int i = tid; i < NF * MM; i += 128) g_gt_key[i] = 0ull;
}

// ---------------- K1: SSD match (per-anchor best gt + per-gt best anchor) ------
__global__ void __launch_bounds__(256) k1_match(const float* __restrict__ gt_boxes,
                                                const int* __restrict__ counts,
                                                const float* __restrict__ anchors) {
    int f = blockIdx.y;
    int tid = threadIdx.x;
    __shared__ float4 sgtb[MM];
    __shared__ float  sga[MM];
    __shared__ int    scount;
    if (tid == 0) scount = counts[f];
    if (tid < MM) {
        float4 b = ((const float4*)gt_boxes)[f * MM + tid];
        sgtb[tid] = b;
        sga[tid] = (b.z - b.x) * (b.w - b.y);
    }
    __syncthreads();
    int count = scount;

    float bI[MM];
    int   bX[MM];
#pragma unroll
    for (int m = 0; m < MM; m++) { bI[m] = -1.f; bX[m] = 0; }

    for (int a = blockIdx.x * 256 + tid; a < AA; a += MB * 256) {
        float4 an = ((const float4*)anchors)[a];
        float ax1 = an.x - 0.5f * an.z, ay1 = an.y - 0.5f * an.w;
        float ax2 = an.x + 0.5f * an.z, ay2 = an.y + 0.5f * an.w;
        float sa = an.z * an.w;
        float aB = -1.f;
        int   aM = 0;
#pragma unroll
        for (int m = 0; m < MM; m++) {
            if (m < count) {
                float4 b = sgtb[m];
                float lx = fmaxf(ax1, b.x), ly = fmaxf(ay1, b.y);
                float rx = fminf(ax2, b.z), ry = fminf(ay2, b.w);
                float w = fmaxf(rx - lx, 0.f), h = fmaxf(ry - ly, 0.f);
                float inter = w * h;
                float uni = sa + sga[m] - inter;
                // rational argmax: avoids a division per IoU
                bool upA = inter > aB * uni;
                bool upG = inter > bI[m] * uni;
                if (upA | upG) {
                    float q = inter / (uni + 1e-10f);
                    if (upA) { aB = q; aM = m; }
                    if (upG) { bI[m] = q; bX[m] = a; }
                }
            }
        }
        g_bt_iou[f * AA + a] = aB;
        g_bt_idx[f * AA + a] = aM;
    }

    // block-reduce per-gt best, then deterministic global atomicMax on packed key
    __shared__ unsigned long long skey[256];
#pragma unroll
    for (int m = 0; m < MM; m++) {
        unsigned long long key = 0ull;
        if (m < count && bI[m] >= 0.f) {
            key = ((unsigned long long)__float_as_uint(bI[m]) << 32) |
                  (unsigned long long)(0xFFFFFFFFu - (unsigned)bX[m]); // smaller idx wins ties
        }
        skey[tid] = key;
        __syncthreads();
        for (int s = 128; s > 0; s >>= 1) {
            if (tid < s) {
                unsigned long long o = skey[tid + s];
                if (o > skey[tid]) skey[tid] = o;
            }
            __syncthreads();
        }
        if (tid == 0 && m < count)
            atomicMax(&g_gt_key[f * MM + m], skey[0]);
        __syncthreads();
    }
}

// ---------------- K2: force each gt's best anchor positive ----------------
__global__ void k2_force(const int* __restrict__ counts) {
    int f = threadIdx.x;
    if (f < NF) {
        int count = counts[f];
        if (count > MM) count = MM;
        for (int m = 0; m < count; m++) {   // sequential: last write wins on collision
            unsigned long long key = g_gt_key[f * MM + m];
            int idx = (int)(0xFFFFFFFFu - (unsigned)(key & 0xFFFFFFFFull));
            g_bt_iou[f * AA + idx] = 2.0f;
            g_bt_idx[f * AA + idx] = m;
        }
    }
}

// ---------------- K3: main loss kernel (regression + CB focal) ----------------
__global__ void __launch_bounds__(256) k3_main(const float* __restrict__ confidence,
                                               const float* __restrict__ pred_loc,
                                               const float* __restrict__ gt_boxes,
                                               const float* __restrict__ gt_labels,
                                               const int* __restrict__ counts,
                                               const float* __restrict__ anchors) {
    int f = blockIdx.y;
    int ab = blockIdx.x * TA;
    int tid = threadIdx.x;

    __shared__ float  gtl_s[MM * CC];
    __shared__ float4 gtb_s[MM];
    __shared__ float  w_s[CC];
    __shared__ int    meta_s[TA];
    __shared__ float  red[256];
    __shared__ int    scount;

    for (int i = tid; i < MM * CC; i += 256) gtl_s[i] = gt_labels[f * MM * CC + i];
    if (tid < MM) gtb_s[tid] = ((const float4*)gt_boxes)[f * MM + tid];
    if (tid < CC) w_s[tid] = g_w[tid];
    if (tid == 0) scount = counts[f];
    __syncthreads();
    int count = scount;

    float myreg = 0.f, mypos = 0.f;
    if (tid < TA) {
        int a = ab + tid;
        float iou = g_bt_iou[f * AA + a];
        int g = g_bt_idx[f * AA + a];
        int meta;
        if (count == 0) meta = -1;          // empty frame -> all ignore
        else if (iou < 0.4f) meta = -2;     // background
        else if (iou < 0.5f) meta = -1;     // ignore band
        else meta = g;                      // positive, matched gt index
        meta_s[tid] = meta;
        if (meta >= 0) {
            mypos = 1.f;
            float4 an = ((const float4*)anchors)[a];
            float4 b = gtb_s[meta];
            float lcx = ((b.x + b.z) * 0.5f - an.x) / (0.1f * an.z);
            float lcy = ((b.y + b.w) * 0.5f - an.y) / (0.1f * an.w);
            float lw = logf(fmaxf(b.z - b.x, 1e-6f) / an.z) * 5.0f;  // /0.2
            float lh = logf(fmaxf(b.w - b.y, 1e-6f) / an.w) * 5.0f;
            float4 pl = ((const float4*)pred_loc)[f * AA + a];
            float n0 = fabsf(pl.x - lcx), n1 = fabsf(pl.y - lcy);
            float n2 = fabsf(pl.z - lw),  n3 = fabsf(pl.w - lh);
            const float SB = 1.f / 9.f;
            myreg  = (n0 < SB ? 4.5f * n0 * n0 : n0 - 0.5f * SB);
            myreg += (n1 < SB ? 4.5f * n1 * n1 : n1 - 0.5f * SB);
            myreg += (n2 < SB ? 4.5f * n2 * n2 : n2 - 0.5f * SB);
            myreg += (n3 < SB ? 4.5f * n3 * n3 : n3 - 0.5f * SB);
        }
    }
    __syncthreads();

    // ---- hot loop: 64 anchors x 80 classes as float4, coalesced ----
    const float4* c4 = (const float4*)(confidence + ((size_t)f * AA + ab) * CC);
    float nsum = 0.f, psum = 0.f;
#pragma unroll
    for (int it = 0; it < (TA * CC / 4) / 256; it++) {   // 5 iters
        int e = it * 256 + tid;                           // < 1280
        int a_l = (int)(((unsigned)e * 52429u) >> 20);    // e / 20
        int cidx = (e - a_l * 20) * 4;
        int meta = meta_s[a_l];
        if (meta != -1) {
            float4 x4 = c4[e];
            float xs[4] = {x4.x, x4.y, x4.z, x4.w};
            if (meta >= 0) {
#pragma unroll
                for (int j = 0; j < 4; j++) {
                    float x = xs[j];
                    float en = __expf(-x);
                    float p = __fdividef(1.f, 1.f + en);
                    float lp = __logf(p);
                    float y = gtl_s[meta * CC + cidx + j];
                    if (y > 0.5f) psum += w_s[cidx + j] * (-lp) * (1.f - p);
                    else          nsum += (x - lp) * p;   // -log(1-p) == x - log(p)
                }
            } else {  // background anchor: all y = 0
#pragma unroll
                for (int j = 0; j < 4; j++) {
                    float x = xs[j];
                    float en = __expf(-x);
                    float p = __fdividef(1.f, 1.f + en);
                    float lp = __logf(p);
                    nsum += (x - lp) * p;
                }
            }
        }
    }
    const float CB1M = 1.0f - 0.9999f;
    float csum = CB1M * nsum + psum;

    // ---- reductions: cls, reg, pos ----
    red[tid] = csum; __syncthreads();
    for (int s = 128; s > 0; s >>= 1) { if (tid < s) red[tid] += red[tid + s]; __syncthreads(); }
    if (tid == 0) atomicAdd(&g_cls_sum, (double)red[0]);
    __syncthreads();
    red[tid] = myreg; __syncthreads();
    for (int s = 128; s > 0; s >>= 1) { if (tid < s) red[tid] += red[tid + s]; __syncthreads(); }
    if (tid == 0) atomicAdd(&g_reg_sum, (double)red[0]);
    __syncthreads();
    red[tid] = mypos; __syncthreads();
    for (int s = 128; s > 0; s >>= 1) { if (tid < s) red[tid] += red[tid + s]; __syncthreads(); }
    if (tid == 0) atomicAdd(&g_pos_cnt, (int)(red[0] + 0.5f));
}

// ---------------- K4: finalize + ego focal loss ----------------
__global__ void k4_final(const float* __restrict__ ego_preds,
                         const int* __restrict__ ego_labels,
                         float* __restrict__ out, int out_size) {
    if (threadIdx.x == 0) {
        float np = fmaxf(1.f, (float)g_pos_cnt);
        float reg = (float)g_reg_sum / (np * 4.f);
        float cls = (float)g_cls_sum / np;

        float col[CE];
        for (int c = 0; c < CE; c++) col[c] = 0.f;
        int nval = 0;
        for (int i = 0; i < NF; i++) {
            int l = ego_labels[i];
            if (l > -1) {
                nval++;
                if (l < CE) col[l] = 1.f;
            }
        }
        float esum = 0.f;
        for (int i = 0; i < NF; i++) {
            if (ego_labels[i] > -1) {
                for (int c = 0; c < CE; c++) {
                    float ep = 1.f / (1.f + expf(-ego_preds[i * CE + c]));
                    ep = fminf(fmaxf(ep, 1e-7f), 1.f - 1e-7f);
                    float oh = col[c];
                    float af = 0.25f * oh + 0.75f * (1.f - oh);
                    float pt = ep * oh + (1.f - ep) * (1.f - oh);
                    float bce = -(oh * logf(ep) + (1.f - oh) * log1pf(-ep));
                    float omp = 1.f - pt;
                    esum += bce * af * omp * omp;
                }
            }
        }
        float ego = (nval > 0) ? esum / fmaxf((float)nval, 1.f) : 0.f;
        if (out_size > 0) out[0] = reg;
        if (out_size > 1) out[1] = cls * 0.125f + ego * 0.25f;
    }
}

extern "C" void kernel_launch(void* const* d_in, const int* in_sizes, int n_in,
                              void* d_out, int out_size) {
    (void)in_sizes; (void)n_in;
    const float* confidence   = (const float*)d_in[0];
    const float* pred_loc     = (const float*)d_in[1];
    const float* gt_boxes     = (const float*)d_in[2];
    const float* gt_labels    = (const float*)d_in[3];
    const int*   counts       = (const int*)d_in[4];
    const float* anchors      = (const float*)d_in[5];
    const float* ego_preds    = (const float*)d_in[6];
    const int*   ego_labels   = (const int*)d_in[7];
    const int*   cls_num_list = (const int*)d_in[8];
    float* out = (float*)d_out;

    k0_init<<<1, 128>>>(cls_num_list);
    k1_match<<<dim3(MB, NF), 256>>>(gt_boxes, counts, anchors);
    k2_force<<<1, 32>>>(counts);
    k3_main<<<dim3(AA / TA, NF), 256>>>(confidence, pred_loc, gt_boxes, gt_labels, counts, anchors);
    k4_final<<<1, 32>>>(ego_preds, ego_labels, out, out_size);
}

// round 3
// speedup vs baseline: 1.4010x; 1.4010x over previous
#include <cuda_runtime.h>
#include <math.h>

#define NF 16          // B*S
#define AA 24000
#define CC 80
#define MM 20
#define CE 7
#define TA 64          // anchors per block in main kernel
#define K1B 24         // blocks_x in match kernel

// ---- device scratch (no allocations allowed) ----
__device__ float              g_bt_iou[NF * AA];
__device__ int                g_bt_idx[NF * AA];
__device__ unsigned long long g_gt_key[NF * MM];
__device__ double             g_cls_sum;
__device__ double             g_reg_sum;
__device__ int                g_pos_cnt;
__device__ float              g_w[CC];

__device__ __forceinline__ float ex2f(float x){ float y; asm("ex2.approx.f32 %0,%1;":"=f"(y):"f"(x)); return y; }
__device__ __forceinline__ float lg2f(float x){ float y; asm("lg2.approx.f32 %0,%1;":"=f"(y):"f"(x)); return y; }
__device__ __forceinline__ float rcpf(float x){ float y; asm("rcp.approx.f32 %0,%1;":"=f"(y):"f"(x)); return y; }

// ---------------- K0: init accumulators + class-balance weights ----------------
__global__ void k0_init(const int* __restrict__ cls_num_list) {
    int tid = threadIdx.x;
    __shared__ float sraw[128];
    __shared__ float ssum;
    float raw = 0.f;
    if (tid < CC) {
        double beta = (double)0.9999f;   // match f32-rounded constant
        double n = (double)cls_num_list[tid];
        raw = (float)((1.0 - beta) / (1.0 - pow(beta, n)));
    }
    sraw[tid] = raw;
    __syncthreads();
    for (int s = 64; s > 0; s >>= 1) {
        if (tid < s) sraw[tid] += sraw[tid + s];
        __syncthreads();
    }
    if (tid == 0) {
        ssum = sraw[0];
        g_cls_sum = 0.0;
        g_reg_sum = 0.0;
        g_pos_cnt = 0;
    }
    __syncthreads();
    if (tid < CC) g_w[tid] = raw / ssum;
    for (int i = tid; i < NF * MM; i += 128) g_gt_key[i] = 0ull;
}

// ---------------- K1: SSD match (per-anchor best gt + per-gt best anchor) ------
__global__ void __launch_bounds__(256) k1_match(const float* __restrict__ gt_boxes,
                                                const int* __restrict__ counts,
                                                const float* __restrict__ anchors) {
    int f = blockIdx.y;
    int tid = threadIdx.x;
    int lane = tid & 31, wrp = tid >> 5;
    __shared__ float4 sgtb[MM];
    __shared__ float  sga[MM];
    __shared__ unsigned long long skey_s[8][MM];
    if (tid < MM) {
        float4 b = ((const float4*)gt_boxes)[f * MM + tid];
        sgtb[tid] = b;
        sga[tid] = (b.z - b.x) * (b.w - b.y);
    }
    __syncthreads();
    int count = counts[f]; if (count > MM) count = MM;

    float    bI[MM];
    unsigned bX[MM];
#pragma unroll
    for (int m = 0; m < MM; m++) { bI[m] = -1.f; bX[m] = 0; }

    for (int a = blockIdx.x * 256 + tid; a < AA; a += K1B * 256) {
        float4 an = ((const float4*)anchors)[a];
        float ax1 = an.x - 0.5f * an.z, ay1 = an.y - 0.5f * an.w;
        float ax2 = an.x + 0.5f * an.z, ay2 = an.y + 0.5f * an.w;
        float sa = an.z * an.w;
        float aB = -1.f;
        int   aM = 0;
#pragma unroll
        for (int m = 0; m < MM; m++) {
            if (m < count) {
                float4 b = sgtb[m];
                float lx = fmaxf(ax1, b.x), ly = fmaxf(ay1, b.y);
                float rx = fminf(ax2, b.z), ry = fminf(ay2, b.w);
                float w = fmaxf(rx - lx, 0.f), h = fmaxf(ry - ly, 0.f);
                float inter = w * h;
                float uni = sa + sga[m] - inter;
                // rational argmax: avoids a division per IoU; strict > keeps first index on ties
                bool upA = inter > aB * uni;
                bool upG = inter > bI[m] * uni;
                if (upA | upG) {
                    float q = inter / (uni + 1e-10f);
                    if (upA) { aB = q; aM = m; }
                    if (upG) { bI[m] = q; bX[m] = (unsigned)a; }
                }
            }
        }
        g_bt_iou[f * AA + a] = aB;
        g_bt_idx[f * AA + a] = aM;
    }

    // per-gt best anchor: warp-shuffle max on packed (iou_bits, ~idx) keys
#pragma unroll
    for (int m = 0; m < MM; m++) {
        unsigned long long key = 0ull;
        if (m < count && bI[m] >= 0.f) {
            key = ((unsigned long long)__float_as_uint(bI[m]) << 32) |
                  (unsigned long long)(0xFFFFFFFFu - bX[m]);   // smaller idx wins ties
        }
#pragma unroll
        for (int o = 16; o > 0; o >>= 1) {
            unsigned long long other = __shfl_down_sync(0xffffffffu, key, o);
            if (other > key) key = other;
        }
        if (lane == 0) skey_s[wrp][m] = key;
    }
    __syncthreads();
    if (tid < MM) {
        unsigned long long k = skey_s[0][tid];
#pragma unroll
        for (int w = 1; w < 8; w++) { unsigned long long o = skey_s[w][tid]; if (o > k) k = o; }
        if (k) atomicMax(&g_gt_key[f * MM + tid], k);
    }
}

// ---------------- K3: main loss kernel (regression + CB focal), force inlined ----
__global__ void __launch_bounds__(256) k3_main(const float* __restrict__ confidence,
                                               const float* __restrict__ pred_loc,
                                               const float* __restrict__ gt_boxes,
                                               const float* __restrict__ gt_labels,
                                               const int* __restrict__ counts,
                                               const float* __restrict__ anchors) {
    int f = blockIdx.y;
    int ab = blockIdx.x * TA;
    int tid = threadIdx.x;
    int lane = tid & 31, wrp = tid >> 5;

    __shared__ unsigned labm_s[MM * 3];   // 80-class bitmask per gt
    __shared__ float  w_s[CC];
    __shared__ int    meta_s[TA];
    __shared__ int    sidx_s[MM];         // forced (best) anchor per gt
    __shared__ float4 gtb_s[MM];
    __shared__ float  redc[8], redr[8], redp[8];

    int count = counts[f]; if (count > MM) count = MM;

    // label bitmasks via ballot (coalesced 32-wide reads)
    const float* gl = gt_labels + (size_t)f * MM * CC;
    for (int m = wrp; m < MM; m += 8) {
        unsigned b0 = __ballot_sync(0xffffffffu, gl[m * CC + lane] > 0.5f);
        unsigned b1 = __ballot_sync(0xffffffffu, gl[m * CC + 32 + lane] > 0.5f);
        unsigned b2 = __ballot_sync(0xffffffffu, (lane < (CC - 64)) ? (gl[m * CC + 64 + lane] > 0.5f) : false);
        if (lane == 0) { labm_s[m * 3] = b0; labm_s[m * 3 + 1] = b1; labm_s[m * 3 + 2] = b2; }
    }
    if (tid < CC) w_s[tid] = g_w[tid];
    if (tid < MM) {
        gtb_s[tid] = ((const float4*)gt_boxes)[f * MM + tid];
        int sidx = -1;
        if (tid < count) {
            unsigned long long key = g_gt_key[f * MM + tid];
            sidx = (int)(0xFFFFFFFFu - (unsigned)(key & 0xFFFFFFFFull));
        }
        sidx_s[tid] = sidx;
    }
    int meta = -1;
    if (tid < TA && count > 0) {
        int a = ab + tid;
        float iou = g_bt_iou[f * AA + a];
        int g = g_bt_idx[f * AA + a];
        meta = (iou < 0.4f) ? -2 : ((iou < 0.5f) ? -1 : g);
    }
    __syncthreads();

    float myreg = 0.f, mypos = 0.f;
    if (tid < TA) {
        int a = ab + tid;
        for (int m = 0; m < count; m++)          // ascending, last write wins (ref scatter)
            if (sidx_s[m] == a) meta = m;
        meta_s[tid] = meta;
        if (meta >= 0) {
            mypos = 1.f;
            float4 an = ((const float4*)anchors)[a];
            float4 b = gtb_s[meta];
            float lcx = ((b.x + b.z) * 0.5f - an.x) / (0.1f * an.z);
            float lcy = ((b.y + b.w) * 0.5f - an.y) / (0.1f * an.w);
            float lw = logf(fmaxf(b.z - b.x, 1e-6f) / an.z) * 5.0f;
            float lh = logf(fmaxf(b.w - b.y, 1e-6f) / an.w) * 5.0f;
            float4 pl = ((const float4*)pred_loc)[f * AA + a];
            float n0 = fabsf(pl.x - lcx), n1 = fabsf(pl.y - lcy);
            float n2 = fabsf(pl.z - lw),  n3 = fabsf(pl.w - lh);
            const float SB = 1.f / 9.f;
            myreg  = (n0 < SB ? 4.5f * n0 * n0 : n0 - 0.5f * SB);
            myreg += (n1 < SB ? 4.5f * n1 * n1 : n1 - 0.5f * SB);
            myreg += (n2 < SB ? 4.5f * n2 * n2 : n2 - 0.5f * SB);
            myreg += (n3 < SB ? 4.5f * n3 * n3 : n3 - 0.5f * SB);
        }
    }
    __syncthreads();

    // ---- hot loop: TA anchors x 80 classes as float4, unified focal math ----
    //   t = x*log2e, u = 2^t, v = 1+u, s = lg2(v), r = 1/v
    //   neg: ln2*s*(1-r)*1e-4        (= softplus(x)*sigmoid(x)*CB1M)
    //   pos: w * ln2*(s-t)*r         (= w*softplus(-x)*sigmoid(-x))
    const float4* c4 = (const float4*)(confidence + ((size_t)f * AA + ab) * CC);
    const float L2E = 1.4426950408889634f;
    const float LN2 = 0.6931471805599453f;
    float nacc = 0.f, pacc = 0.f;
#pragma unroll
    for (int it = 0; it < (TA * CC / 4) / 256; it++) {   // 5 iters
        int e = it * 256 + tid;                           // < 1280
        int a_l = (int)(((unsigned)e * 52429u) >> 20);    // e / 20
        int cbase = (e - a_l * 20) * 4;
        int m = meta_s[a_l];
        if (m != -1) {
            float4 x4 = __ldcs(c4 + e);
            unsigned mbits = 0u;
            if (m >= 0) mbits = (labm_s[m * 3 + (cbase >> 5)] >> (cbase & 31)) & 0xFu;
            float xs[4] = {x4.x, x4.y, x4.z, x4.w};
#pragma unroll
            for (int j = 0; j < 4; j++) {
                float x = xs[j];
                float t = x * L2E;
                float u = ex2f(t);
                float v = 1.f + u;
                float s = lg2f(v);
                float r = rcpf(v);
                if ((mbits >> j) & 1) pacc = fmaf(w_s[cbase + j] * (s - t), r, pacc);
                else                  nacc = fmaf(s, 1.f - r, nacc);
            }
        }
    }
    const float CB1M = 1.0f - 0.9999f;
    float csum = LN2 * fmaf(CB1M, nacc, pacc);

    // ---- block reductions via shuffles, one atomic each ----
#pragma unroll
    for (int o = 16; o > 0; o >>= 1) {
        csum  += __shfl_down_sync(0xffffffffu, csum, o);
        myreg += __shfl_down_sync(0xffffffffu, myreg, o);
        mypos += __shfl_down_sync(0xffffffffu, mypos, o);
    }
    if (lane == 0) { redc[wrp] = csum; redr[wrp] = myreg; redp[wrp] = mypos; }
    __syncthreads();
    if (tid == 0) {
        float c = 0.f, r = 0.f, p = 0.f;
#pragma unroll
        for (int w = 0; w < 8; w++) { c += redc[w]; r += redr[w]; p += redp[w]; }
        atomicAdd(&g_cls_sum, (double)c);
        if (r != 0.f) atomicAdd(&g_reg_sum, (double)r);
        if (p != 0.f) atomicAdd(&g_pos_cnt, (int)(p + 0.5f));
    }
}

// ---------------- K4: finalize + ego focal loss (parallel) ----------------
__global__ void k4_final(const float* __restrict__ ego_preds,
                         const int* __restrict__ ego_labels,
                         float* __restrict__ out, int out_size) {
    __shared__ float col_s[CE];
    __shared__ int nval_s;
    __shared__ float red_s[4];
    int tid = threadIdx.x;
    if (tid < CE) col_s[tid] = 0.f;
    if (tid == 0) nval_s = 0;
    __syncthreads();
    if (tid < NF) {
        int l = ego_labels[tid];
        if (l > -1) { atomicAdd(&nval_s, 1); if (l < CE) col_s[l] = 1.f; }
    }
    __syncthreads();
    float term = 0.f;
    if (tid < NF * CE) {
        int i = tid / CE, c = tid - i * CE;
        if (ego_labels[i] > -1) {
            float x = ego_preds[tid];
            float ep = 1.f / (1.f + expf(-x));
            ep = fminf(fmaxf(ep, 1e-7f), 1.f - 1e-7f);
            float oh = col_s[c];
            float af = 0.25f * oh + 0.75f * (1.f - oh);
            float pt = ep * oh + (1.f - ep) * (1.f - oh);
            float bce = -(oh * logf(ep) + (1.f - oh) * log1pf(-ep));
            float omp = 1.f - pt;
            term = bce * af * omp * omp;
        }
    }
#pragma unroll
    for (int o = 16; o > 0; o >>= 1) term += __shfl_down_sync(0xffffffffu, term, o);
    if ((tid & 31) == 0) red_s[tid >> 5] = term;
    __syncthreads();
    if (tid == 0) {
        float esum = red_s[0] + red_s[1] + red_s[2] + red_s[3];
        int nval = nval_s;
        float ego = (nval > 0) ? esum / fmaxf((float)nval, 1.f) : 0.f;
        float np = fmaxf(1.f, (float)g_pos_cnt);
        float reg = (float)g_reg_sum / (np * 4.f);
        float cls = (float)g_cls_sum / np;
        if (out_size > 0) out[0] = reg;
        if (out_size > 1) out[1] = cls * 0.125f + ego * 0.25f;
    }
}

extern "C" void kernel_launch(void* const* d_in, const int* in_sizes, int n_in,
                              void* d_out, int out_size) {
    (void)in_sizes; (void)n_in;
    const float* confidence   = (const float*)d_in[0];
    const float* pred_loc     = (const float*)d_in[1];
    const float* gt_boxes     = (const float*)d_in[2];
    const float* gt_labels    = (const float*)d_in[3];
    const int*   counts       = (const int*)d_in[4];
    const float* anchors      = (const float*)d_in[5];
    const float* ego_preds    = (const float*)d_in[6];
    const int*   ego_labels   = (const int*)d_in[7];
    const int*   cls_num_list = (const int*)d_in[8];
    float* out = (float*)d_out;

    k0_init<<<1, 128>>>(cls_num_list);
    k1_match<<<dim3(K1B, NF), 256>>>(gt_boxes, counts, anchors);
    k3_main<<<dim3(AA / TA, NF), 256>>>(confidence, pred_loc, gt_boxes, gt_labels, counts, anchors);
    k4_final<<<1, 128>>>(ego_preds, ego_labels, out, out_size);
}